// round 16
// baseline (speedup 1.0000x reference)
#include <cuda_runtime.h>
#include <cstdint>

// Depth2normal: per-pixel 3x3 plane fit via smallest eigenvector of 4x4 Gram
// matrix AtA of rows [x,y,z,1] (valid-masked), then normalize + sign-flip.
//
// Issue-slot-bound. This revision:
//  - 4 Jacobi sweeps (3 sweeps measured FAIL at 3.1e-2; 4 sweeps = 1.2e-5)
//  - fully branchless rotations (no divergent guard): eps folded into h^2,
//    copysign denominator; apq==0 degenerates to exact identity rotation
//  - sweep loop force-unrolled: sweep-1 eigvec updates constant-fold against
//    the identity v; ptxas DCE removes dead a-updates in the final sweep

#define KH 480
#define KW 640
#define HWC (KH * KW)
#define D_MIN 0.0f
#define D_MAX 10.0f
#define MIN_NGHBR 4

// Upper-triangle access with compile-time index normalization.
#define AE(P, Q) a[(P) < (Q) ? (P) : (Q)][(P) < (Q) ? (Q) : (P)]

// Branchless Jacobi rotation on pair (P,Q).
//   h2 = d^2 + apq^2 + 1e-30  (strictly positive -> rsqrt finite)
//   den = d + copysign(sqrt(h2), d)   (|den| >= sqrt(h2) > 0)
//   t = apq / den   (apq==0 -> t=0 -> c=1,s=0 -> exact identity)
#define JROT(P, Q)                                                          \
    do {                                                                    \
        float apq = AE(P, Q);                                               \
        float app = AE(P, P), aqq = AE(Q, Q);                               \
        float d = 0.5f * (aqq - app);                                       \
        float h2 = fmaf(d, d, fmaf(apq, apq, 1e-30f));                      \
        float r = h2 * rsqrtf(h2);            /* sqrt(h2), 1 MUFU */        \
        float den = d + copysignf(r, d);                                    \
        float t = __fdividef(apq, den);                                     \
        float c = rsqrtf(fmaf(t, t, 1.0f));                                 \
        float s = t * c;                                                    \
        float ta = t * apq;                                                 \
        AE(P, P) = app - ta;                                                \
        AE(Q, Q) = aqq + ta;                                                \
        AE(P, Q) = 0.0f;                                                    \
        _Pragma("unroll")                                                   \
        for (int r_ = 0; r_ < 4; ++r_) {                                    \
            if (r_ != (P) && r_ != (Q)) {                                   \
                float arp = AE(r_, P), arq = AE(r_, Q);                     \
                AE(r_, P) = fmaf(c, arp, -s * arq);                         \
                AE(r_, Q) = fmaf(s, arp, c * arq);                          \
            }                                                               \
        }                                                                   \
        _Pragma("unroll")                                                   \
        for (int r_ = 0; r_ < 3; ++r_) {                                    \
            float vp = v[r_][P], vq = v[r_][Q];                             \
            v[r_][P] = fmaf(c, vp, -s * vq);                                \
            v[r_][Q] = fmaf(s, vp, c * vq);                                 \
        }                                                                   \
    } while (0)

#define ACCUM(x, y, z, valid)                                               \
    do {                                                                    \
        if (valid) {                                                        \
            sxx = fmaf(x, x, sxx); sxy = fmaf(x, y, sxy);                   \
            sxz = fmaf(x, z, sxz); sx += (x);                               \
            syy = fmaf(y, y, syy); syz = fmaf(y, z, syz); sy += (y);        \
            szz = fmaf(z, z, szz); sz += (z);                               \
            cnt += 1.0f;                                                    \
        }                                                                   \
    } while (0)

__global__ __launch_bounds__(256)
void depth2normal_kernel(const float* __restrict__ pts,
                         float* __restrict__ out_normal,
                         float* __restrict__ out_mask,
                         int B) {
    int idx = blockIdx.x * blockDim.x + threadIdx.x;
    int total = B * HWC;
    if (idx >= total) return;

    int w = idx % KW;
    int h = (idx / KW) % KH;
    int b = idx / HWC;

    int base = h * KW + w;
    const float* p = pts + (size_t)b * 3 * HWC + base;

    float sxx = 0.f, sxy = 0.f, sxz = 0.f, sx = 0.f;
    float syy = 0.f, syz = 0.f, sy = 0.f;
    float szz = 0.f, sz = 0.f, cnt = 0.f;
    float cx, cy, cz;
    bool center_valid;

    bool interior = (h > 0) & (h < KH - 1) & (w > 0) & (w < KW - 1);
    if (interior) {
        // Unchecked loads: constant offsets fold into LDG immediates.
#pragma unroll
        for (int di = -1; di <= 1; ++di) {
#pragma unroll
            for (int dj = -1; dj <= 1; ++dj) {
                const int o = di * KW + dj;
                float x = __ldg(p + o);
                float y = __ldg(p + o + HWC);
                float z = __ldg(p + o + 2 * HWC);
                bool val = (z > D_MIN) & (z < D_MAX);
                if (di == 0 && dj == 0) { cx = x; cy = y; cz = z; center_valid = val; }
                ACCUM(x, y, z, val);
            }
        }
    } else {
#pragma unroll
        for (int di = -1; di <= 1; ++di) {
#pragma unroll
            for (int dj = -1; dj <= 1; ++dj) {
                int hh = h + di, ww = w + dj;
                bool inb = ((unsigned)hh < (unsigned)KH) & ((unsigned)ww < (unsigned)KW);
                const int o = di * KW + dj;
                float x = 0.f, y = 0.f, z = 0.f;
                if (inb) {
                    x = __ldg(p + o);
                    y = __ldg(p + o + HWC);
                    z = __ldg(p + o + 2 * HWC);
                }
                bool val = inb & (z > D_MIN) & (z < D_MAX);
                if (di == 0 && dj == 0) { cx = x; cy = y; cz = z; center_valid = val; }
                ACCUM(x, y, z, val);
            }
        }
    }

    // Upper triangle of AtA.
    float a[4][4];
    a[0][0] = sxx; a[0][1] = sxy; a[0][2] = sxz; a[0][3] = sx;
    a[1][1] = syy; a[1][2] = syz; a[1][3] = sy;
    a[2][2] = szz; a[2][3] = sz;
    a[3][3] = cnt;

    // Eigenvector accumulator, rows 0..2 only (row 3 never read).
    float v[3][4];
#pragma unroll
    for (int i = 0; i < 3; ++i)
#pragma unroll
        for (int j = 0; j < 4; ++j)
            v[i][j] = (i == j) ? 1.0f : 0.0f;

    // Cyclic Jacobi, 4 sweeps (convergence floor), fully unrolled.
#pragma unroll
    for (int sw = 0; sw < 4; ++sw) {
        JROT(0, 1);
        JROT(0, 2);
        JROT(0, 3);
        JROT(1, 2);
        JROT(1, 3);
        JROT(2, 3);
    }

    // argmin eigenvalue on the diagonal.
    float bd = a[0][0];
    float e0 = v[0][0], e1 = v[1][0], e2 = v[2][0];
    if (a[1][1] < bd) { bd = a[1][1]; e0 = v[0][1]; e1 = v[1][1]; e2 = v[2][1]; }
    if (a[2][2] < bd) { bd = a[2][2]; e0 = v[0][2]; e1 = v[1][2]; e2 = v[2][2]; }
    if (a[3][3] < bd) { bd = a[3][3]; e0 = v[0][3]; e1 = v[1][3]; e2 = v[2][3]; }

    // Normalize first 3 components via clamped rsqrt.
    float ss = fmaf(e0, e0, fmaf(e1, e1, e2 * e2));
    float inv = rsqrtf(fmaxf(ss, 1e-24f));
    float nx = e0 * inv, ny = e1 * inv, nz = e2 * inv;

    // Sign flip toward the center point; sign(0)=0 zeroes the normal.
    float dot = fmaf(nx, cx, fmaf(ny, cy, nz * cz));
    float flip = (dot > 0.f) ? 1.0f : ((dot < 0.f) ? -1.0f : 0.0f);
    nx *= flip; ny *= flip; nz *= flip;

    // Validity mask (squared-norm compare, no sqrt).
    float n2sq = fmaf(nx, nx, fmaf(ny, ny, nz * nz));
    bool vm = center_valid && (cnt >= (float)MIN_NGHBR) && (n2sq > 0.25f);

    size_t pix = (size_t)base;
    out_normal[((size_t)b * 3 + 0) * HWC + pix] = nx;
    out_normal[((size_t)b * 3 + 1) * HWC + pix] = ny;
    out_normal[((size_t)b * 3 + 2) * HWC + pix] = nz;
    out_mask[(size_t)b * HWC + pix] = vm ? 1.0f : 0.0f;
}

extern "C" void kernel_launch(void* const* d_in, const int* in_sizes, int n_in,
                              void* d_out, int out_size) {
    const float* pts = (const float*)d_in[0];
    float* out = (float*)d_out;

    int B = in_sizes[0] / (3 * HWC);   // points is (B,3,H,W)

    float* out_normal = out;                        // (B,3,H,W)
    float* out_mask = out + (size_t)B * 3 * HWC;    // (B,1,H,W)

    int total = B * HWC;
    int threads = 256;
    int blocks = (total + threads - 1) / threads;
    depth2normal_kernel<<<blocks, threads>>>(pts, out_normal, out_mask, B);
}

// round 17
// speedup vs baseline: 1.0120x; 1.0120x over previous
#include <cuda_runtime.h>
#include <cstdint>

// Depth2normal: per-pixel 3x3 plane fit via smallest eigenvector of 4x4 Gram
// matrix AtA of rows [x,y,z,1] (valid-masked), then normalize + sign-flip.
//
// Issue-slot-bound. This revision:
//  - 4 Jacobi sweeps (3 sweeps measured FAIL at 3.1e-2; 4 sweeps = 1.2e-5)
//  - fully branchless rotations (no divergent guard): eps folded into h^2,
//    copysign denominator; apq==0 degenerates to exact identity rotation
//  - sweep loop force-unrolled: sweep-1 eigvec updates constant-fold against
//    the identity v; ptxas DCE removes dead a-updates in the final sweep

#define KH 480
#define KW 640
#define HWC (KH * KW)
#define D_MIN 0.0f
#define D_MAX 10.0f
#define MIN_NGHBR 4

// Upper-triangle access with compile-time index normalization.
#define AE(P, Q) a[(P) < (Q) ? (P) : (Q)][(P) < (Q) ? (Q) : (P)]

// Branchless Jacobi rotation on pair (P,Q).
//   h2 = d^2 + apq^2 + 1e-30  (strictly positive -> rsqrt finite)
//   den = d + copysign(sqrt(h2), d)   (|den| >= sqrt(h2) > 0)
//   t = apq / den   (apq==0 -> t=0 -> c=1,s=0 -> exact identity)
#define JROT(P, Q)                                                          \
    do {                                                                    \
        float apq = AE(P, Q);                                               \
        float app = AE(P, P), aqq = AE(Q, Q);                               \
        float d = 0.5f * (aqq - app);                                       \
        float h2 = fmaf(d, d, fmaf(apq, apq, 1e-30f));                      \
        float r = h2 * rsqrtf(h2);            /* sqrt(h2), 1 MUFU */        \
        float den = d + copysignf(r, d);                                    \
        float t = __fdividef(apq, den);                                     \
        float c = rsqrtf(fmaf(t, t, 1.0f));                                 \
        float s = t * c;                                                    \
        float ta = t * apq;                                                 \
        AE(P, P) = app - ta;                                                \
        AE(Q, Q) = aqq + ta;                                                \
        AE(P, Q) = 0.0f;                                                    \
        _Pragma("unroll")                                                   \
        for (int r_ = 0; r_ < 4; ++r_) {                                    \
            if (r_ != (P) && r_ != (Q)) {                                   \
                float arp = AE(r_, P), arq = AE(r_, Q);                     \
                AE(r_, P) = fmaf(c, arp, -s * arq);                         \
                AE(r_, Q) = fmaf(s, arp, c * arq);                          \
            }                                                               \
        }                                                                   \
        _Pragma("unroll")                                                   \
        for (int r_ = 0; r_ < 3; ++r_) {                                    \
            float vp = v[r_][P], vq = v[r_][Q];                             \
            v[r_][P] = fmaf(c, vp, -s * vq);                                \
            v[r_][Q] = fmaf(s, vp, c * vq);                                 \
        }                                                                   \
    } while (0)

#define ACCUM(x, y, z, valid)                                               \
    do {                                                                    \
        if (valid) {                                                        \
            sxx = fmaf(x, x, sxx); sxy = fmaf(x, y, sxy);                   \
            sxz = fmaf(x, z, sxz); sx += (x);                               \
            syy = fmaf(y, y, syy); syz = fmaf(y, z, syz); sy += (y);        \
            szz = fmaf(z, z, szz); sz += (z);                               \
            cnt += 1.0f;                                                    \
        }                                                                   \
    } while (0)

__global__ __launch_bounds__(256)
void depth2normal_kernel(const float* __restrict__ pts,
                         float* __restrict__ out_normal,
                         float* __restrict__ out_mask,
                         int B) {
    int idx = blockIdx.x * blockDim.x + threadIdx.x;
    int total = B * HWC;
    if (idx >= total) return;

    int w = idx % KW;
    int h = (idx / KW) % KH;
    int b = idx / HWC;

    int base = h * KW + w;
    const float* p = pts + (size_t)b * 3 * HWC + base;

    float sxx = 0.f, sxy = 0.f, sxz = 0.f, sx = 0.f;
    float syy = 0.f, syz = 0.f, sy = 0.f;
    float szz = 0.f, sz = 0.f, cnt = 0.f;
    float cx, cy, cz;
    bool center_valid;

    bool interior = (h > 0) & (h < KH - 1) & (w > 0) & (w < KW - 1);
    if (interior) {
        // Unchecked loads: constant offsets fold into LDG immediates.
#pragma unroll
        for (int di = -1; di <= 1; ++di) {
#pragma unroll
            for (int dj = -1; dj <= 1; ++dj) {
                const int o = di * KW + dj;
                float x = __ldg(p + o);
                float y = __ldg(p + o + HWC);
                float z = __ldg(p + o + 2 * HWC);
                bool val = (z > D_MIN) & (z < D_MAX);
                if (di == 0 && dj == 0) { cx = x; cy = y; cz = z; center_valid = val; }
                ACCUM(x, y, z, val);
            }
        }
    } else {
#pragma unroll
        for (int di = -1; di <= 1; ++di) {
#pragma unroll
            for (int dj = -1; dj <= 1; ++dj) {
                int hh = h + di, ww = w + dj;
                bool inb = ((unsigned)hh < (unsigned)KH) & ((unsigned)ww < (unsigned)KW);
                const int o = di * KW + dj;
                float x = 0.f, y = 0.f, z = 0.f;
                if (inb) {
                    x = __ldg(p + o);
                    y = __ldg(p + o + HWC);
                    z = __ldg(p + o + 2 * HWC);
                }
                bool val = inb & (z > D_MIN) & (z < D_MAX);
                if (di == 0 && dj == 0) { cx = x; cy = y; cz = z; center_valid = val; }
                ACCUM(x, y, z, val);
            }
        }
    }

    // Upper triangle of AtA.
    float a[4][4];
    a[0][0] = sxx; a[0][1] = sxy; a[0][2] = sxz; a[0][3] = sx;
    a[1][1] = syy; a[1][2] = syz; a[1][3] = sy;
    a[2][2] = szz; a[2][3] = sz;
    a[3][3] = cnt;

    // Eigenvector accumulator, rows 0..2 only (row 3 never read).
    float v[3][4];
#pragma unroll
    for (int i = 0; i < 3; ++i)
#pragma unroll
        for (int j = 0; j < 4; ++j)
            v[i][j] = (i == j) ? 1.0f : 0.0f;

    // Cyclic Jacobi, 4 sweeps (convergence floor), fully unrolled.
#pragma unroll
    for (int sw = 0; sw < 4; ++sw) {
        JROT(0, 1);
        JROT(0, 2);
        JROT(0, 3);
        JROT(1, 2);
        JROT(1, 3);
        JROT(2, 3);
    }

    // argmin eigenvalue on the diagonal.
    float bd = a[0][0];
    float e0 = v[0][0], e1 = v[1][0], e2 = v[2][0];
    if (a[1][1] < bd) { bd = a[1][1]; e0 = v[0][1]; e1 = v[1][1]; e2 = v[2][1]; }
    if (a[2][2] < bd) { bd = a[2][2]; e0 = v[0][2]; e1 = v[1][2]; e2 = v[2][2]; }
    if (a[3][3] < bd) { bd = a[3][3]; e0 = v[0][3]; e1 = v[1][3]; e2 = v[2][3]; }

    // Normalize first 3 components via clamped rsqrt.
    float ss = fmaf(e0, e0, fmaf(e1, e1, e2 * e2));
    float inv = rsqrtf(fmaxf(ss, 1e-24f));
    float nx = e0 * inv, ny = e1 * inv, nz = e2 * inv;

    // Sign flip toward the center point; sign(0)=0 zeroes the normal.
    float dot = fmaf(nx, cx, fmaf(ny, cy, nz * cz));
    float flip = (dot > 0.f) ? 1.0f : ((dot < 0.f) ? -1.0f : 0.0f);
    nx *= flip; ny *= flip; nz *= flip;

    // Validity mask (squared-norm compare, no sqrt).
    float n2sq = fmaf(nx, nx, fmaf(ny, ny, nz * nz));
    bool vm = center_valid && (cnt >= (float)MIN_NGHBR) && (n2sq > 0.25f);

    size_t pix = (size_t)base;
    out_normal[((size_t)b * 3 + 0) * HWC + pix] = nx;
    out_normal[((size_t)b * 3 + 1) * HWC + pix] = ny;
    out_normal[((size_t)b * 3 + 2) * HWC + pix] = nz;
    out_mask[(size_t)b * HWC + pix] = vm ? 1.0f : 0.0f;
}

extern "C" void kernel_launch(void* const* d_in, const int* in_sizes, int n_in,
                              void* d_out, int out_size) {
    const float* pts = (const float*)d_in[0];
    float* out = (float*)d_out;

    int B = in_sizes[0] / (3 * HWC);   // points is (B,3,H,W)

    float* out_normal = out;                        // (B,3,H,W)
    float* out_mask = out + (size_t)B * 3 * HWC;    // (B,1,H,W)

    int total = B * HWC;
    int threads = 256;
    int blocks = (total + threads - 1) / threads;
    depth2normal_kernel<<<blocks, threads>>>(pts, out_normal, out_mask, B);
}